// round 1
// baseline (speedup 1.0000x reference)
#include <cuda_runtime.h>
#include <cuda_bf16.h>
#include <stdint.h>

// Problem constants
#define BB    16
#define NN    100000
#define CC    30
#define NC    (NN * CC)           // 3,000,000
#define TOT   (BB * NC)           // 48,000,000
#define PAIRS (BB * CC)           // 480
#define CAP   1024                // candidate buffer per (b,c)
#define PRE   200                 // PRE_NMS_TOPK
#define MAXDET 100
#define NWORDS 7                  // ceil(200/32)

#define COLLECT_T    0.995f
#define SCORE_T      0.01f
#define NMS_T        0.5f

// Output layout (flattened float32, concatenation of the 5 outputs)
#define OUT_BOXES  0
#define OUT_SCORES (BB * MAXDET * 4)                  // 6400
#define OUT_LABELS (OUT_SCORES + BB * MAXDET)         // 8000
#define OUT_ROT    (OUT_LABELS + BB * MAXDET)         // 9600
#define OUT_TR     (OUT_ROT + BB * MAXDET * 3)        // 14400

// Scratch (device globals; no allocation allowed)
__device__ unsigned long long g_cand[PAIRS * CAP];    // packed (score_bits<<32)|~n
__device__ int                g_cnt[PAIRS];
__device__ unsigned long long g_ckey[PAIRS * PRE];    // compacted survivors: (score_bits<<32)|(0xFFFFFFFF-pos)
__device__ int                g_cidx[PAIRS * PRE];    // survivor anchor index n
__device__ int                g_scnt[PAIRS];

// ---------------------------------------------------------------------------
__global__ void k_init() {
    int t = threadIdx.x;
    if (t < PAIRS) g_cnt[t] = 0;
}

// ---------------------------------------------------------------------------
// Pass 1: stream classification, append candidates with score > COLLECT_T.
__global__ void k_scan(const float* __restrict__ cls) {
    const float4* c4 = reinterpret_cast<const float4*>(cls);
    int stride = gridDim.x * blockDim.x;
    for (int i4 = blockIdx.x * blockDim.x + threadIdx.x; i4 < TOT / 4; i4 += stride) {
        float4 v = __ldg(&c4[i4]);
        int base = i4 * 4;
        float vs[4] = {v.x, v.y, v.z, v.w};
#pragma unroll
        for (int k = 0; k < 4; k++) {
            float s = vs[k];
            if (s > COLLECT_T) {
                int i = base + k;
                int b = i / NC;
                int r = i - b * NC;
                int n = r / CC;
                int c = r - n * CC;
                int pair = b * CC + c;
                int pos = atomicAdd(&g_cnt[pair], 1);
                if (pos < CAP) {
                    g_cand[pair * CAP + pos] =
                        ((unsigned long long)__float_as_uint(s) << 32) | (unsigned)(~n);
                }
            }
        }
    }
}

// ---------------------------------------------------------------------------
// Pass 2: per (b,c): exact top-200 (bitonic sort of candidates), greedy NMS
// via bitmask matrix, compact survivors in rank order.
__global__ void __launch_bounds__(256) k_select(const float* __restrict__ cls,
                                                const float* __restrict__ boxes) {
    __shared__ unsigned long long s_keys[CAP];
    __shared__ float s_x1[PRE], s_y1[PRE], s_x2[PRE], s_y2[PRE], s_ar[PRE];
    __shared__ unsigned s_sup[PRE * NWORDS];
    __shared__ unsigned s_keep[NWORDS];
    __shared__ unsigned long long s_red[256];

    int tid  = threadIdx.x;
    int pair = blockIdx.x;
    int b    = pair / CC;
    int c    = pair - b * CC;

    int M = g_cnt[pair];
    if (M > CAP) M = CAP;

    for (int j = tid; j < CAP; j += 256)
        s_keys[j] = (j < M) ? g_cand[pair * CAP + j] : 0ULL;
    __syncthreads();

    if (M >= PRE) {
        // Bitonic sort, descending, 1024 u64 keys.
        for (int k2 = 2; k2 <= CAP; k2 <<= 1) {
            for (int j = k2 >> 1; j > 0; j >>= 1) {
                for (int t = tid; t < CAP; t += 256) {
                    int l = t ^ j;
                    if (l > t) {
                        unsigned long long a = s_keys[t], d = s_keys[l];
                        bool desc = ((t & k2) == 0);
                        if ((a < d) == desc) { s_keys[t] = d; s_keys[l] = a; }
                    }
                }
                __syncthreads();
            }
        }
    } else {
        // Fallback (statistically never taken): exact top-200 by repeated
        // bounded argmax over the full strided column.
        unsigned long long prev = 0xFFFFFFFFFFFFFFFFULL;
        for (int k = 0; k < PRE; k++) {
            unsigned long long best = 0ULL;
            for (int n = tid; n < NN; n += 256) {
                float s = cls[(size_t)(b * NN + n) * CC + c];
                if (s > SCORE_T) {
                    unsigned long long key =
                        ((unsigned long long)__float_as_uint(s) << 32) | (unsigned)(~n);
                    if (key < prev && key > best) best = key;
                }
            }
            s_red[tid] = best;
            __syncthreads();
            for (int st = 128; st > 0; st >>= 1) {
                if (tid < st && s_red[tid + st] > s_red[tid]) s_red[tid] = s_red[tid + st];
                __syncthreads();
            }
            if (tid == 0) s_keys[k] = s_red[0];
            __syncthreads();
            prev = s_keys[k];
        }
        __syncthreads();
    }

    // Gather top-200 boxes
    if (tid < PRE) {
        unsigned long long key = s_keys[tid];
        if (key != 0ULL) {
            unsigned n = ~(unsigned)(key & 0xFFFFFFFFULL);
            const float4* bp = reinterpret_cast<const float4*>(boxes);
            float4 bx = __ldg(&bp[(size_t)b * NN + n]);
            s_x1[tid] = bx.x; s_y1[tid] = bx.y; s_x2[tid] = bx.z; s_y2[tid] = bx.w;
            s_ar[tid] = fmaxf(bx.z - bx.x, 0.f) * fmaxf(bx.w - bx.y, 0.f);
        } else {
            s_x1[tid] = 0.f; s_y1[tid] = 0.f; s_x2[tid] = 0.f; s_y2[tid] = 0.f;
            s_ar[tid] = 0.f;
        }
    }
    __syncthreads();

    // Suppression bit matrix: row i, bit j set if (j>i && iou(i,j)>0.5)
    if (tid < PRE) {
        float x1 = s_x1[tid], y1 = s_y1[tid], x2 = s_x2[tid], y2 = s_y2[tid];
        float ai = s_ar[tid];
#pragma unroll
        for (int w = 0; w < NWORDS; w++) {
            unsigned word = 0u;
            int jbase = w * 32;
#pragma unroll 4
            for (int jj = 0; jj < 32; jj++) {
                int j = jbase + jj;
                if (j < PRE && j > tid) {
                    float xx1 = fmaxf(x1, s_x1[j]);
                    float yy1 = fmaxf(y1, s_y1[j]);
                    float xx2 = fminf(x2, s_x2[j]);
                    float yy2 = fminf(y2, s_y2[j]);
                    float inter = fmaxf(xx2 - xx1, 0.f) * fmaxf(yy2 - yy1, 0.f);
                    float uni = ai + s_ar[j] - inter;
                    float iou = inter / fmaxf(uni, 1e-8f);
                    if (iou > NMS_T) word |= (1u << jj);
                }
            }
            s_sup[tid * NWORDS + w] = word;
        }
    }

    // Validity ballot (warps 0..6 cover 224 slots)
    {
        int w = tid >> 5, lane = tid & 31;
        int j = tid;
        bool val = (j < PRE) && (s_keys[j] != 0ULL);
        unsigned bal = __ballot_sync(0xFFFFFFFFu, val);
        if (w < NWORDS && lane == 0) s_keep[w] = bal;
    }
    __syncthreads();

    // Warp 0: sequential keep resolution + compaction
    if (tid < 32) {
        int lane = tid;
        unsigned kw = (lane < NWORDS) ? s_keep[lane] : 0u;
        for (int i = 0; i < PRE; i++) {
            unsigned ow = __shfl_sync(0xFFFFFFFFu, kw, i >> 5);
            if ((ow >> (i & 31)) & 1u) {
                if (lane < NWORDS) kw &= ~s_sup[i * NWORDS + lane];
            }
        }
        // compaction in rank order
        int offset = 0;
        for (int chunk = 0; chunk < NWORDS; chunk++) {
            unsigned bits = __shfl_sync(0xFFFFFFFFu, kw, chunk);
            int j = chunk * 32 + lane;
            bool kp = (bits >> lane) & 1u;
            if (kp) {
                int rank = offset + __popc(bits & ((1u << lane) - 1u));
                unsigned long long key = s_keys[j];
                unsigned n   = ~(unsigned)(key & 0xFFFFFFFFULL);
                unsigned pos = (unsigned)(c * PRE + j);
                g_ckey[pair * PRE + rank] =
                    (key & 0xFFFFFFFF00000000ULL) | (unsigned long long)(0xFFFFFFFFu - pos);
                g_cidx[pair * PRE + rank] = (int)n;
            }
            offset += __popc(bits);
        }
        if (lane == 0) g_scnt[pair] = offset;
    }
}

// ---------------------------------------------------------------------------
// Pass 3: per image — 30-way merge of sorted survivor lists (exact top-100
// with jax tie-break), then gather + write outputs.
__global__ void __launch_bounds__(128) k_merge(const float* __restrict__ boxes,
                                               const float* __restrict__ rot,
                                               const float* __restrict__ tr,
                                               float* __restrict__ out) {
    __shared__ int   s_idx[MAXDET];
    __shared__ float s_score[MAXDET];
    __shared__ int   s_lab[MAXDET];
    __shared__ int   s_ns;

    int tid = threadIdx.x;
    int b   = blockIdx.x;

    if (tid < 32) {
        int lane = tid;
        int cnt = 0, ptr = 0;
        unsigned long long head = 0ULL;
        if (lane < CC) {
            cnt = g_scnt[b * CC + lane];
            head = (ptr < cnt) ? g_ckey[(b * CC + lane) * PRE + 0] : 0ULL;
        }
        int ns = MAXDET;
        for (int t = 0; t < MAXDET; t++) {
            unsigned long long m = head;
#pragma unroll
            for (int o = 16; o; o >>= 1) {
                unsigned long long other = __shfl_xor_sync(0xFFFFFFFFu, m, o);
                if (other > m) m = other;
            }
            if (m == 0ULL) { ns = t; break; }
            if (head == m) {
                s_score[t] = __uint_as_float((unsigned)(m >> 32));
                s_idx[t]   = g_cidx[(b * CC + lane) * PRE + ptr];
                s_lab[t]   = lane;
                ptr++;
                head = (ptr < cnt) ? g_ckey[(b * CC + lane) * PRE + ptr] : 0ULL;
            }
        }
        if (lane == 0) s_ns = ns;
    }
    __syncthreads();

    int ns = s_ns;
    for (int t = tid; t < MAXDET; t += 128) {
        if (t < ns) {
            int idx = s_idx[t];
            const float4* bp = reinterpret_cast<const float4*>(boxes);
            float4 bx = __ldg(&bp[(size_t)b * NN + idx]);
            out[OUT_BOXES + (b * MAXDET + t) * 4 + 0] = bx.x;
            out[OUT_BOXES + (b * MAXDET + t) * 4 + 1] = bx.y;
            out[OUT_BOXES + (b * MAXDET + t) * 4 + 2] = bx.z;
            out[OUT_BOXES + (b * MAXDET + t) * 4 + 3] = bx.w;
            out[OUT_SCORES + b * MAXDET + t] = s_score[t];
            out[OUT_LABELS + b * MAXDET + t] = (float)s_lab[t];
            size_t rb = ((size_t)b * NN + idx) * 3;
#pragma unroll
            for (int k = 0; k < 3; k++) {
                out[OUT_ROT + (b * MAXDET + t) * 3 + k] = __ldg(&rot[rb + k]);
                out[OUT_TR  + (b * MAXDET + t) * 3 + k] = __ldg(&tr[rb + k]);
            }
        } else {
#pragma unroll
            for (int k = 0; k < 4; k++) out[OUT_BOXES + (b * MAXDET + t) * 4 + k] = -1.0f;
            out[OUT_SCORES + b * MAXDET + t] = -1.0f;
            out[OUT_LABELS + b * MAXDET + t] = -1.0f;
#pragma unroll
            for (int k = 0; k < 3; k++) {
                out[OUT_ROT + (b * MAXDET + t) * 3 + k] = -1.0f;
                out[OUT_TR  + (b * MAXDET + t) * 3 + k] = -1.0f;
            }
        }
    }
}

// ---------------------------------------------------------------------------
extern "C" void kernel_launch(void* const* d_in, const int* in_sizes, int n_in,
                              void* d_out, int out_size) {
    const float* boxes = (const float*)d_in[0];
    const float* cls   = (const float*)d_in[1];
    const float* rot   = (const float*)d_in[2];
    const float* tr    = (const float*)d_in[3];
    float* out = (float*)d_out;

    k_init<<<1, 512>>>();
    k_scan<<<2048, 256>>>(cls);
    k_select<<<PAIRS, 256>>>(cls, boxes);
    k_merge<<<BB, 128>>>(boxes, rot, tr, out);
}

// round 3
// speedup vs baseline: 1.5448x; 1.5448x over previous
#include <cuda_runtime.h>
#include <cuda_bf16.h>
#include <stdint.h>

// Problem constants
#define BB    16
#define NN    100000
#define CC    30
#define NC    (NN * CC)           // 3,000,000
#define TOT   (BB * NC)           // 48,000,000
#define PAIRS (BB * CC)           // 480
#define CAP   512                 // candidate buffer per (b,c)
#define PRE   200                 // PRE_NMS_TOPK
#define MAXDET 100
#define NWORDS 7                  // ceil(200/32)
#define NWP    8                  // padded row stride (words)
#define ROWS_PAD 224              // 7*32
#define MPC    16                 // merge candidates per class
#define MCAND  512                // 480 padded to power of two

#define COLLECT_T    0.997f
#define SCORE_T      0.01f
#define NMS_T        0.5f

// Output layout (flattened float32 concat of the 5 outputs)
#define OUT_BOXES  0
#define OUT_SCORES (BB * MAXDET * 4)
#define OUT_LABELS (OUT_SCORES + BB * MAXDET)
#define OUT_ROT    (OUT_LABELS + BB * MAXDET)
#define OUT_TR     (OUT_ROT + BB * MAXDET * 3)

// Scratch (device globals; zero-initialized at module load)
__device__ unsigned long long g_cand[PAIRS * CAP];   // packed (score_bits<<32)|~n
__device__ int                g_cnt[PAIRS];
__device__ unsigned long long g_ckey[PAIRS * PRE];   // survivors by compacted rank:
                                                     // (score_bits<<32)|(0xFFFFFFFF-(c*PRE+j_orig))
__device__ int                g_nidx[PAIRS * PRE];   // anchor index keyed by ORIGINAL rank j_orig
__device__ int                g_scnt[PAIRS];

// ---------------------------------------------------------------------------
// Pass 1: stream classification, append candidates with score > COLLECT_T.
__global__ void k_scan(const float* __restrict__ cls) {
    const float4* c4 = reinterpret_cast<const float4*>(cls);
    int stride = gridDim.x * blockDim.x;
    for (int i4 = blockIdx.x * blockDim.x + threadIdx.x; i4 < TOT / 4; i4 += stride) {
        float4 v = __ldg(&c4[i4]);
        float m = fmaxf(fmaxf(v.x, v.y), fmaxf(v.z, v.w));
        if (m > COLLECT_T) {
            int base = i4 * 4;
            float vs[4] = {v.x, v.y, v.z, v.w};
#pragma unroll
            for (int k = 0; k < 4; k++) {
                float s = vs[k];
                if (s > COLLECT_T) {
                    int i = base + k;
                    int b = i / NC;
                    int r = i - b * NC;
                    int n = r / CC;
                    int c = r - n * CC;
                    int pair = b * CC + c;
                    int pos = atomicAdd(&g_cnt[pair], 1);
                    if (pos < CAP) {
                        g_cand[pair * CAP + pos] =
                            ((unsigned long long)__float_as_uint(s) << 32) | (unsigned)(~n);
                    }
                }
            }
        }
    }
}

// ---------------------------------------------------------------------------
// Pass 2: per (b,c): exact top-200 (bitonic sort of candidates), greedy NMS
// via bitmask matrix with chunked warp resolution, compact survivors.
__global__ void __launch_bounds__(256) k_select(const float* __restrict__ cls,
                                                const float* __restrict__ boxes) {
    __shared__ unsigned long long s_keys[CAP];
    __shared__ float4  s_box[PRE];
    __shared__ float   s_ar[PRE];
    __shared__ unsigned s_sup[ROWS_PAD * NWP];
    __shared__ unsigned s_keep[NWORDS];
    __shared__ unsigned long long s_red[256];

    int tid  = threadIdx.x;
    int pair = blockIdx.x;
    int b    = pair / CC;
    int c    = pair - b * CC;

    int M = g_cnt[pair];          // true count (may exceed CAP)
    int Mc = (M > CAP) ? CAP : M;

    for (int j = tid; j < CAP; j += 256)
        s_keys[j] = (j < Mc) ? g_cand[pair * CAP + j] : 0ULL;
    __syncthreads();
    if (tid == 0) g_cnt[pair] = 0;   // reset for next graph replay

    if (M >= PRE && M <= CAP) {
        // Bitonic sort, descending, 512 u64 keys, 256 threads = 1 exchange each.
        for (int k2 = 2; k2 <= CAP; k2 <<= 1) {
            for (int j = k2 >> 1; j > 0; j >>= 1) {
                int i = ((tid & ~(j - 1)) << 1) | (tid & (j - 1));
                int l = i | j;
                unsigned long long a = s_keys[i], d = s_keys[l];
                bool desc = ((i & k2) == 0);
                if ((a < d) == desc) { s_keys[i] = d; s_keys[l] = a; }
                __syncthreads();
            }
        }
    } else {
        // Exact fallback (statistically never taken): repeated bounded argmax
        // over the full column with the reference SCORE_T mask.
        unsigned long long prev = 0xFFFFFFFFFFFFFFFFULL;
        for (int k = 0; k < PRE; k++) {
            unsigned long long best = 0ULL;
            for (int n = tid; n < NN; n += 256) {
                float s = cls[(size_t)(b * NN + n) * CC + c];
                if (s > SCORE_T) {
                    unsigned long long key =
                        ((unsigned long long)__float_as_uint(s) << 32) | (unsigned)(~n);
                    if (key < prev && key > best) best = key;
                }
            }
            s_red[tid] = best;
            __syncthreads();
            for (int st = 128; st > 0; st >>= 1) {
                if (tid < st && s_red[tid + st] > s_red[tid]) s_red[tid] = s_red[tid + st];
                __syncthreads();
            }
            if (tid == 0) s_keys[k] = s_red[0];
            __syncthreads();
            prev = s_keys[k];
        }
        __syncthreads();
    }

    // Gather top-200 boxes
    if (tid < PRE) {
        unsigned long long key = s_keys[tid];
        if (key != 0ULL) {
            unsigned n = ~(unsigned)(key & 0xFFFFFFFFULL);
            const float4* bp = reinterpret_cast<const float4*>(boxes);
            float4 bx = __ldg(&bp[(size_t)b * NN + n]);
            s_box[tid] = bx;
            s_ar[tid]  = fmaxf(bx.z - bx.x, 0.f) * fmaxf(bx.w - bx.y, 0.f);
        } else {
            s_box[tid] = make_float4(0.f, 0.f, 0.f, 0.f);
            s_ar[tid]  = 0.f;
        }
    }
    __syncthreads();

    // Suppression bit matrix: row i, bit j set iff (j>i && iou(i,j)>0.5).
    if (tid < PRE) {
        float4 bi = s_box[tid];
        float ai = s_ar[tid];
#pragma unroll
        for (int w = 0; w < NWORDS; w++) {
            unsigned word = 0u;
            int jbase = w * 32;
#pragma unroll 4
            for (int jj = 0; jj < 32; jj++) {
                int j = jbase + jj;
                if (j < PRE && j > tid) {
                    float4 bj = s_box[j];
                    float xx1 = fmaxf(bi.x, bj.x);
                    float yy1 = fmaxf(bi.y, bj.y);
                    float xx2 = fminf(bi.z, bj.z);
                    float yy2 = fminf(bi.w, bj.w);
                    float inter = fmaxf(xx2 - xx1, 0.f) * fmaxf(yy2 - yy1, 0.f);
                    float uni = ai + s_ar[j] - inter;
                    float iou = inter / fmaxf(uni, 1e-8f);
                    if (iou > NMS_T) word |= (1u << jj);
                }
            }
            s_sup[tid * NWP + w] = word;
        }
    } else if (tid < ROWS_PAD) {
#pragma unroll
        for (int w = 0; w < NWORDS; w++) s_sup[tid * NWP + w] = 0u;
    }

    // Validity ballot (warps 0..6 cover 224 slots)
    {
        int w = tid >> 5, lane = tid & 31;
        bool val = (tid < PRE) && (s_keys[tid] != 0ULL);
        unsigned bal = __ballot_sync(0xFFFFFFFFu, val);
        if (w < NWORDS && lane == 0) s_keep[w] = bal;
    }
    __syncthreads();

    // Warp 0: chunked greedy NMS resolution + compaction.
    if (tid < 32) {
        int lane = tid;
        unsigned kw = (lane < NWORDS) ? s_keep[lane] : 0u;
        for (int cch = 0; cch < NWORDS; cch++) {
            unsigned cur = __shfl_sync(0xFFFFFFFFu, kw, cch);
            // Intra-chunk resolve: one lane, all in registers.
            if (lane == 0) {
                unsigned d[32];
#pragma unroll
                for (int jj = 0; jj < 32; jj++)
                    d[jj] = s_sup[(cch * 32 + jj) * NWP + cch];
#pragma unroll
                for (int jj = 0; jj < 32; jj++)
                    if ((cur >> jj) & 1u) cur &= ~d[jj];
            }
            cur = __shfl_sync(0xFFFFFFFFu, cur, 0);
            if (lane == cch) kw = cur;
            // Inter-chunk suppression: word owners accumulate in parallel.
            if (lane > cch && lane < NWORDS) {
                unsigned acc = 0u;
#pragma unroll
                for (int jj = 0; jj < 32; jj++)
                    if ((cur >> jj) & 1u) acc |= s_sup[(cch * 32 + jj) * NWP + lane];
                kw &= ~acc;
            }
        }
        // Compaction in rank order.
        int offset = 0;
        for (int chunk = 0; chunk < NWORDS; chunk++) {
            unsigned bits = __shfl_sync(0xFFFFFFFFu, kw, chunk);
            int j = chunk * 32 + lane;
            bool kp = (bits >> lane) & 1u;
            if (kp) {
                int rank = offset + __popc(bits & ((1u << lane) - 1u));
                unsigned long long key = s_keys[j];
                unsigned n   = ~(unsigned)(key & 0xFFFFFFFFULL);
                unsigned pos = (unsigned)(c * PRE + j);   // j = ORIGINAL top-200 rank
                g_ckey[pair * PRE + rank] =
                    (key & 0xFFFFFFFF00000000ULL) | (unsigned long long)(0xFFFFFFFFu - pos);
                g_nidx[pair * PRE + j] = (int)n;
            }
            offset += __popc(bits);
        }
        if (lane == 0) g_scnt[pair] = offset;
    }
}

// ---------------------------------------------------------------------------
// Pass 3: per image — exact top-100 via sort of first-16-per-class survivor
// keys (with exact saturation check + rare exact fallback), then output.
__global__ void __launch_bounds__(256) k_merge(const float* __restrict__ boxes,
                                               const float* __restrict__ rot,
                                               const float* __restrict__ tr,
                                               float* __restrict__ out) {
    __shared__ unsigned long long s_keys[MCAND];
    __shared__ int   s_scnt[CC];
    __shared__ int   s_ccnt[CC];
    __shared__ int   s_flag;
    __shared__ int   s_idx[MAXDET];
    __shared__ float s_score[MAXDET];
    __shared__ int   s_lab[MAXDET];

    int tid = threadIdx.x;
    int b   = blockIdx.x;

    if (tid == 0) s_flag = 0;
    if (tid < CC) { s_scnt[tid] = g_scnt[b * CC + tid]; s_ccnt[tid] = 0; }
    if (tid < MAXDET) s_idx[tid] = -1;
    __syncthreads();

    // Load candidates: slot t -> class t/16, compacted rank t%16.
    for (int t = tid; t < MCAND; t += 256) {
        unsigned long long key = 0ULL;
        if (t < CC * MPC) {
            int cc = t >> 4, j = t & 15;
            if (j < s_scnt[cc]) key = g_ckey[(b * CC + cc) * PRE + j];
        }
        s_keys[t] = key;
    }
    __syncthreads();

    // Bitonic sort, descending, 512 u64 keys.
    for (int k2 = 2; k2 <= MCAND; k2 <<= 1) {
        for (int j = k2 >> 1; j > 0; j >>= 1) {
            int i = ((tid & ~(j - 1)) << 1) | (tid & (j - 1));
            int l = i | j;
            unsigned long long a = s_keys[i], d = s_keys[l];
            bool desc = ((i & k2) == 0);
            if ((a < d) == desc) { s_keys[i] = d; s_keys[l] = a; }
            __syncthreads();
        }
    }

    // Saturation check: class contributed all 16 candidates to top-100 while
    // having more survivors -> candidate set may be incomplete -> fallback.
    if (tid < MAXDET) {
        unsigned long long key = s_keys[tid];
        if (key != 0ULL) {
            unsigned pos = 0xFFFFFFFFu - (unsigned)(key & 0xFFFFFFFFULL);
            atomicAdd(&s_ccnt[pos / PRE], 1);
        }
    }
    __syncthreads();
    if (tid < CC && s_ccnt[tid] >= MPC && s_scnt[tid] > MPC) s_flag = 1;
    __syncthreads();

    if (!s_flag) {
        if (tid < MAXDET) {
            unsigned long long key = s_keys[tid];
            if (key != 0ULL) {
                unsigned pos = 0xFFFFFFFFu - (unsigned)(key & 0xFFFFFFFFULL);
                int cc = pos / PRE;
                int jo = pos - cc * PRE;
                s_score[tid] = __uint_as_float((unsigned)(key >> 32));
                s_lab[tid]   = cc;
                s_idx[tid]   = g_nidx[(b * CC + cc) * PRE + jo];
            }
        }
    } else if (tid < 32) {
        // Exact fallback: serial 30-way merge over full survivor lists.
        int lane = tid;
        int cnt = 0, ptr = 0;
        unsigned long long head = 0ULL;
        if (lane < CC) {
            cnt = s_scnt[lane];
            head = (ptr < cnt) ? g_ckey[(b * CC + lane) * PRE + 0] : 0ULL;
        }
        for (int t = 0; t < MAXDET; t++) {
            unsigned long long m = head;
#pragma unroll
            for (int o = 16; o; o >>= 1) {
                unsigned long long other = __shfl_xor_sync(0xFFFFFFFFu, m, o);
                if (other > m) m = other;
            }
            if (m == 0ULL) break;
            if (head == m) {
                unsigned pos = 0xFFFFFFFFu - (unsigned)(m & 0xFFFFFFFFULL);
                int jo = pos - lane * PRE;
                s_score[t] = __uint_as_float((unsigned)(m >> 32));
                s_lab[t]   = lane;
                s_idx[t]   = g_nidx[(b * CC + lane) * PRE + jo];
                ptr++;
                head = (ptr < cnt) ? g_ckey[(b * CC + lane) * PRE + ptr] : 0ULL;
            }
        }
    }
    __syncthreads();

    // Output
    for (int t = tid; t < MAXDET; t += 256) {
        int idx = s_idx[t];
        if (idx >= 0) {
            const float4* bp = reinterpret_cast<const float4*>(boxes);
            float4 bx = __ldg(&bp[(size_t)b * NN + idx]);
            out[OUT_BOXES + (b * MAXDET + t) * 4 + 0] = bx.x;
            out[OUT_BOXES + (b * MAXDET + t) * 4 + 1] = bx.y;
            out[OUT_BOXES + (b * MAXDET + t) * 4 + 2] = bx.z;
            out[OUT_BOXES + (b * MAXDET + t) * 4 + 3] = bx.w;
            out[OUT_SCORES + b * MAXDET + t] = s_score[t];
            out[OUT_LABELS + b * MAXDET + t] = (float)s_lab[t];
            size_t rb = ((size_t)b * NN + idx) * 3;
#pragma unroll
            for (int k = 0; k < 3; k++) {
                out[OUT_ROT + (b * MAXDET + t) * 3 + k] = __ldg(&rot[rb + k]);
                out[OUT_TR  + (b * MAXDET + t) * 3 + k] = __ldg(&tr[rb + k]);
            }
        } else {
#pragma unroll
            for (int k = 0; k < 4; k++) out[OUT_BOXES + (b * MAXDET + t) * 4 + k] = -1.0f;
            out[OUT_SCORES + b * MAXDET + t] = -1.0f;
            out[OUT_LABELS + b * MAXDET + t] = -1.0f;
#pragma unroll
            for (int k = 0; k < 3; k++) {
                out[OUT_ROT + (b * MAXDET + t) * 3 + k] = -1.0f;
                out[OUT_TR  + (b * MAXDET + t) * 3 + k] = -1.0f;
            }
        }
    }
}

// ---------------------------------------------------------------------------
extern "C" void kernel_launch(void* const* d_in, const int* in_sizes, int n_in,
                              void* d_out, int out_size) {
    const float* boxes = (const float*)d_in[0];
    const float* cls   = (const float*)d_in[1];
    const float* rot   = (const float*)d_in[2];
    const float* tr    = (const float*)d_in[3];
    float* out = (float*)d_out;

    k_scan<<<2048, 256>>>(cls);
    k_select<<<PAIRS, 256>>>(cls, boxes);
    k_merge<<<BB, 256>>>(boxes, rot, tr, out);
}

// round 4
// speedup vs baseline: 1.6464x; 1.0658x over previous
#include <cuda_runtime.h>
#include <cuda_bf16.h>
#include <stdint.h>

// Problem constants
#define BB    16
#define NN    100000
#define CC    30
#define NC    (NN * CC)           // 3,000,000
#define TOT   (BB * NC)           // 48,000,000
#define PAIRS (BB * CC)           // 480
#define CAP   512                 // candidate buffer per (b,c)
#define PRE   200                 // PRE_NMS_TOPK
#define MAXDET 100
#define NWORDS 7                  // ceil(200/32)
#define NWP    8                  // padded row stride (words)
#define ROWS_PAD 224              // 7*32
#define MPC    16                 // merge candidates per class
#define MCAND  512                // 480 padded to power of two

#define COLLECT_T    0.997f
#define SCORE_T      0.01f
#define NMS_T        0.5f

// Output layout (flattened float32 concat of the 5 outputs)
#define OUT_BOXES  0
#define OUT_SCORES (BB * MAXDET * 4)
#define OUT_LABELS (OUT_SCORES + BB * MAXDET)
#define OUT_ROT    (OUT_LABELS + BB * MAXDET)
#define OUT_TR     (OUT_ROT + BB * MAXDET * 3)

// Scratch (device globals; zero-initialized at module load)
__device__ unsigned long long g_cand[PAIRS * CAP];   // packed (score_bits<<32)|~n
__device__ int                g_cnt[PAIRS];
__device__ unsigned long long g_ckey[PAIRS * PRE];   // survivors by compacted rank
__device__ int                g_nidx[PAIRS * PRE];   // anchor index keyed by ORIGINAL rank
__device__ int                g_scnt[PAIRS];

// ---------------------------------------------------------------------------
// Pass 1: stream classification, append candidates with score > COLLECT_T.
__device__ __forceinline__ void scan_proc(float4 v, int i4) {
    float m = fmaxf(fmaxf(v.x, v.y), fmaxf(v.z, v.w));
    if (m > COLLECT_T) {
        int base = i4 * 4;
        float vs[4] = {v.x, v.y, v.z, v.w};
#pragma unroll
        for (int k = 0; k < 4; k++) {
            float s = vs[k];
            if (s > COLLECT_T) {
                int i = base + k;
                int b = i / NC;
                int r = i - b * NC;
                int n = r / CC;
                int c = r - n * CC;
                int pair = b * CC + c;
                int pos = atomicAdd(&g_cnt[pair], 1);
                if (pos < CAP) {
                    g_cand[pair * CAP + pos] =
                        ((unsigned long long)__float_as_uint(s) << 32) | (unsigned)(~n);
                }
            }
        }
    }
}

__global__ void k_scan(const float* __restrict__ cls) {
    const float4* c4 = reinterpret_cast<const float4*>(cls);
    const int NIT = TOT / 4;
    int T = gridDim.x * blockDim.x;
    int i = blockIdx.x * blockDim.x + threadIdx.x;
    for (; i + 3 * T < NIT; i += 4 * T) {
        float4 a = __ldg(&c4[i]);
        float4 b = __ldg(&c4[i + T]);
        float4 c = __ldg(&c4[i + 2 * T]);
        float4 d = __ldg(&c4[i + 3 * T]);
        scan_proc(a, i);
        scan_proc(b, i + T);
        scan_proc(c, i + 2 * T);
        scan_proc(d, i + 3 * T);
    }
    for (; i < NIT; i += T)
        scan_proc(__ldg(&c4[i]), i);
}

// ---------------------------------------------------------------------------
// Pass 2: per (b,c): exact top-200 via hybrid register/shfl bitonic sort,
// greedy NMS via bitmask matrix with chunked warp resolution, compaction.
__global__ void __launch_bounds__(256) k_select(const float* __restrict__ cls,
                                                const float* __restrict__ boxes) {
    __shared__ unsigned long long s_x[CAP];      // sort exchange / fallback reduce
    __shared__ unsigned long long s_keys[256];   // final top-256 (descending)
    __shared__ float4  s_box[PRE];
    __shared__ float   s_ar[PRE];
    __shared__ unsigned s_sup[ROWS_PAD * NWP];
    __shared__ unsigned s_keep[NWORDS];

    int tid  = threadIdx.x;
    int pair = blockIdx.x;
    int b    = pair / CC;
    int c    = pair - b * CC;

    int M = g_cnt[pair];          // true count (may exceed CAP); reset in k_merge
    int Mc = (M > CAP) ? CAP : M;

    if (M >= PRE && M <= CAP) {
        // Hybrid bitonic sort: 512 u64, 2 per thread (positions tid, tid+256).
        unsigned long long v0 = (tid < Mc)       ? g_cand[pair * CAP + tid]       : 0ULL;
        unsigned long long v1 = (tid + 256 < Mc) ? g_cand[pair * CAP + tid + 256] : 0ULL;

#pragma unroll
        for (int k2 = 2; k2 <= 512; k2 <<= 1) {
#pragma unroll
            for (int j = k2 >> 1; j > 0; j >>= 1) {
                if (j == 256) {
                    // in-thread pair (tid, tid+256), descending region
                    if (v0 < v1) { unsigned long long t = v0; v0 = v1; v1 = t; }
                } else if (j >= 32) {
                    s_x[tid] = v0; s_x[tid + 256] = v1;
                    __syncthreads();
                    unsigned long long o0 = s_x[tid ^ j];
                    unsigned long long o1 = s_x[(tid ^ j) + 256];
                    bool up = (tid & j) != 0;
                    bool d0 = ((tid & k2) == 0);
                    bool d1 = (((tid + 256) & k2) == 0);
                    v0 = (up == d0) ? (v0 < o0 ? v0 : o0) : (v0 > o0 ? v0 : o0);
                    v1 = (up == d1) ? (v1 < o1 ? v1 : o1) : (v1 > o1 ? v1 : o1);
                    __syncthreads();
                } else {
                    unsigned long long o0 = __shfl_xor_sync(0xFFFFFFFFu, v0, j);
                    unsigned long long o1 = __shfl_xor_sync(0xFFFFFFFFu, v1, j);
                    bool up = (tid & j) != 0;
                    bool d0 = ((tid & k2) == 0);
                    bool d1 = (((tid + 256) & k2) == 0);
                    v0 = (up == d0) ? (v0 < o0 ? v0 : o0) : (v0 > o0 ? v0 : o0);
                    v1 = (up == d1) ? (v1 < o1 ? v1 : o1) : (v1 > o1 ? v1 : o1);
                }
            }
        }
        s_keys[tid] = v0;   // positions 0..255 = 256 largest, descending
        __syncthreads();
    } else {
        // Exact fallback (statistically never taken): repeated bounded argmax
        // over the full column with the reference SCORE_T mask.
        unsigned long long prev = 0xFFFFFFFFFFFFFFFFULL;
        if (tid < 256 && tid >= PRE) s_keys[tid] = 0ULL;
        for (int k = 0; k < PRE; k++) {
            unsigned long long best = 0ULL;
            for (int n = tid; n < NN; n += 256) {
                float s = cls[(size_t)(b * NN + n) * CC + c];
                if (s > SCORE_T) {
                    unsigned long long key =
                        ((unsigned long long)__float_as_uint(s) << 32) | (unsigned)(~n);
                    if (key < prev && key > best) best = key;
                }
            }
            s_x[tid] = best;
            __syncthreads();
            for (int st = 128; st > 0; st >>= 1) {
                if (tid < st && s_x[tid + st] > s_x[tid]) s_x[tid] = s_x[tid + st];
                __syncthreads();
            }
            if (tid == 0) s_keys[k] = s_x[0];
            __syncthreads();
            prev = s_keys[k];
        }
        __syncthreads();
    }

    // Gather top-200 boxes
    if (tid < PRE) {
        unsigned long long key = s_keys[tid];
        if (key != 0ULL) {
            unsigned n = ~(unsigned)(key & 0xFFFFFFFFULL);
            const float4* bp = reinterpret_cast<const float4*>(boxes);
            float4 bx = __ldg(&bp[(size_t)b * NN + n]);
            s_box[tid] = bx;
            s_ar[tid]  = fmaxf(bx.z - bx.x, 0.f) * fmaxf(bx.w - bx.y, 0.f);
        } else {
            s_box[tid] = make_float4(0.f, 0.f, 0.f, 0.f);
            s_ar[tid]  = 0.f;
        }
    }
    __syncthreads();

    // Suppression bit matrix: row i, bit j set iff (j>i && iou(i,j)>0.5).
    if (tid < PRE) {
        float4 bi = s_box[tid];
        float ai = s_ar[tid];
#pragma unroll
        for (int w = 0; w < NWORDS; w++) {
            unsigned word = 0u;
            int jbase = w * 32;
#pragma unroll 4
            for (int jj = 0; jj < 32; jj++) {
                int j = jbase + jj;
                if (j < PRE && j > tid) {
                    float4 bj = s_box[j];
                    float xx1 = fmaxf(bi.x, bj.x);
                    float yy1 = fmaxf(bi.y, bj.y);
                    float xx2 = fminf(bi.z, bj.z);
                    float yy2 = fminf(bi.w, bj.w);
                    float inter = fmaxf(xx2 - xx1, 0.f) * fmaxf(yy2 - yy1, 0.f);
                    float uni = ai + s_ar[j] - inter;
                    float iou = inter / fmaxf(uni, 1e-8f);
                    if (iou > NMS_T) word |= (1u << jj);
                }
            }
            s_sup[tid * NWP + w] = word;
        }
    } else if (tid < ROWS_PAD) {
#pragma unroll
        for (int w = 0; w < NWORDS; w++) s_sup[tid * NWP + w] = 0u;
    }

    // Validity ballot (warps 0..6 cover 224 slots)
    {
        int w = tid >> 5, lane = tid & 31;
        bool val = (tid < PRE) && (s_keys[tid] != 0ULL);
        unsigned bal = __ballot_sync(0xFFFFFFFFu, val);
        if (w < NWORDS && lane == 0) s_keep[w] = bal;
    }
    __syncthreads();

    // Warp 0: chunked greedy NMS resolution + compaction.
    if (tid < 32) {
        int lane = tid;
        unsigned kw = (lane < NWORDS) ? s_keep[lane] : 0u;
        for (int cch = 0; cch < NWORDS; cch++) {
            unsigned cur = __shfl_sync(0xFFFFFFFFu, kw, cch);
            // Intra-chunk resolve: one lane, all in registers.
            if (lane == 0) {
                unsigned d[32];
#pragma unroll
                for (int jj = 0; jj < 32; jj++)
                    d[jj] = s_sup[(cch * 32 + jj) * NWP + cch];
#pragma unroll
                for (int jj = 0; jj < 32; jj++)
                    if ((cur >> jj) & 1u) cur &= ~d[jj];
            }
            cur = __shfl_sync(0xFFFFFFFFu, cur, 0);
            if (lane == cch) kw = cur;
            // Inter-chunk suppression: word owners accumulate in parallel.
            if (lane > cch && lane < NWORDS) {
                unsigned acc = 0u;
#pragma unroll
                for (int jj = 0; jj < 32; jj++)
                    if ((cur >> jj) & 1u) acc |= s_sup[(cch * 32 + jj) * NWP + lane];
                kw &= ~acc;
            }
        }
        // Compaction in rank order.
        int offset = 0;
        for (int chunk = 0; chunk < NWORDS; chunk++) {
            unsigned bits = __shfl_sync(0xFFFFFFFFu, kw, chunk);
            int j = chunk * 32 + lane;
            bool kp = (bits >> lane) & 1u;
            if (kp) {
                int rank = offset + __popc(bits & ((1u << lane) - 1u));
                unsigned long long key = s_keys[j];
                unsigned n   = ~(unsigned)(key & 0xFFFFFFFFULL);
                unsigned pos = (unsigned)(c * PRE + j);   // j = ORIGINAL top-200 rank
                g_ckey[pair * PRE + rank] =
                    (key & 0xFFFFFFFF00000000ULL) | (unsigned long long)(0xFFFFFFFFu - pos);
                g_nidx[pair * PRE + j] = (int)n;
            }
            offset += __popc(bits);
        }
        if (lane == 0) g_scnt[pair] = offset;
    }
}

// ---------------------------------------------------------------------------
// Pass 3: per image — exact top-100 via sort of first-16-per-class survivor
// keys (with exact saturation check + rare exact fallback), then output.
__global__ void __launch_bounds__(256) k_merge(const float* __restrict__ boxes,
                                               const float* __restrict__ rot,
                                               const float* __restrict__ tr,
                                               float* __restrict__ out) {
    __shared__ unsigned long long s_keys[MCAND];
    __shared__ int   s_scnt[CC];
    __shared__ int   s_ccnt[CC];
    __shared__ int   s_flag;
    __shared__ int   s_idx[MAXDET];
    __shared__ float s_score[MAXDET];
    __shared__ int   s_lab[MAXDET];

    int tid = threadIdx.x;
    int b   = blockIdx.x;

    if (tid == 0) s_flag = 0;
    if (tid < CC) {
        s_scnt[tid] = g_scnt[b * CC + tid];
        s_ccnt[tid] = 0;
        g_cnt[b * CC + tid] = 0;   // reset scan counters for next graph replay
    }
    if (tid < MAXDET) s_idx[tid] = -1;
    __syncthreads();

    // Load candidates: slot t -> class t/16, compacted rank t%16.
    for (int t = tid; t < MCAND; t += 256) {
        unsigned long long key = 0ULL;
        if (t < CC * MPC) {
            int cc = t >> 4, j = t & 15;
            if (j < s_scnt[cc]) key = g_ckey[(b * CC + cc) * PRE + j];
        }
        s_keys[t] = key;
    }
    __syncthreads();

    // Bitonic sort, descending, 512 u64 keys.
    for (int k2 = 2; k2 <= MCAND; k2 <<= 1) {
        for (int j = k2 >> 1; j > 0; j >>= 1) {
            int i = ((tid & ~(j - 1)) << 1) | (tid & (j - 1));
            int l = i | j;
            unsigned long long a = s_keys[i], d = s_keys[l];
            bool desc = ((i & k2) == 0);
            if ((a < d) == desc) { s_keys[i] = d; s_keys[l] = a; }
            __syncthreads();
        }
    }

    // Saturation check: class contributed all 16 candidates to top-100 while
    // having more survivors -> candidate set may be incomplete -> fallback.
    if (tid < MAXDET) {
        unsigned long long key = s_keys[tid];
        if (key != 0ULL) {
            unsigned pos = 0xFFFFFFFFu - (unsigned)(key & 0xFFFFFFFFULL);
            atomicAdd(&s_ccnt[pos / PRE], 1);
        }
    }
    __syncthreads();
    if (tid < CC && s_ccnt[tid] >= MPC && s_scnt[tid] > MPC) s_flag = 1;
    __syncthreads();

    if (!s_flag) {
        if (tid < MAXDET) {
            unsigned long long key = s_keys[tid];
            if (key != 0ULL) {
                unsigned pos = 0xFFFFFFFFu - (unsigned)(key & 0xFFFFFFFFULL);
                int cc = pos / PRE;
                int jo = pos - cc * PRE;
                s_score[tid] = __uint_as_float((unsigned)(key >> 32));
                s_lab[tid]   = cc;
                s_idx[tid]   = g_nidx[(b * CC + cc) * PRE + jo];
            }
        }
    } else if (tid < 32) {
        // Exact fallback: serial 30-way merge over full survivor lists.
        int lane = tid;
        int cnt = 0, ptr = 0;
        unsigned long long head = 0ULL;
        if (lane < CC) {
            cnt = s_scnt[lane];
            head = (ptr < cnt) ? g_ckey[(b * CC + lane) * PRE + 0] : 0ULL;
        }
        for (int t = 0; t < MAXDET; t++) {
            unsigned long long m = head;
#pragma unroll
            for (int o = 16; o; o >>= 1) {
                unsigned long long other = __shfl_xor_sync(0xFFFFFFFFu, m, o);
                if (other > m) m = other;
            }
            if (m == 0ULL) break;
            if (head == m) {
                unsigned pos = 0xFFFFFFFFu - (unsigned)(m & 0xFFFFFFFFULL);
                int jo = pos - lane * PRE;
                s_score[t] = __uint_as_float((unsigned)(m >> 32));
                s_lab[t]   = lane;
                s_idx[t]   = g_nidx[(b * CC + lane) * PRE + jo];
                ptr++;
                head = (ptr < cnt) ? g_ckey[(b * CC + lane) * PRE + ptr] : 0ULL;
            }
        }
    }
    __syncthreads();

    // Output
    for (int t = tid; t < MAXDET; t += 256) {
        int idx = s_idx[t];
        if (idx >= 0) {
            const float4* bp = reinterpret_cast<const float4*>(boxes);
            float4 bx = __ldg(&bp[(size_t)b * NN + idx]);
            out[OUT_BOXES + (b * MAXDET + t) * 4 + 0] = bx.x;
            out[OUT_BOXES + (b * MAXDET + t) * 4 + 1] = bx.y;
            out[OUT_BOXES + (b * MAXDET + t) * 4 + 2] = bx.z;
            out[OUT_BOXES + (b * MAXDET + t) * 4 + 3] = bx.w;
            out[OUT_SCORES + b * MAXDET + t] = s_score[t];
            out[OUT_LABELS + b * MAXDET + t] = (float)s_lab[t];
            size_t rb = ((size_t)b * NN + idx) * 3;
#pragma unroll
            for (int k = 0; k < 3; k++) {
                out[OUT_ROT + (b * MAXDET + t) * 3 + k] = __ldg(&rot[rb + k]);
                out[OUT_TR  + (b * MAXDET + t) * 3 + k] = __ldg(&tr[rb + k]);
            }
        } else {
#pragma unroll
            for (int k = 0; k < 4; k++) out[OUT_BOXES + (b * MAXDET + t) * 4 + k] = -1.0f;
            out[OUT_SCORES + b * MAXDET + t] = -1.0f;
            out[OUT_LABELS + b * MAXDET + t] = -1.0f;
#pragma unroll
            for (int k = 0; k < 3; k++) {
                out[OUT_ROT + (b * MAXDET + t) * 3 + k] = -1.0f;
                out[OUT_TR  + (b * MAXDET + t) * 3 + k] = -1.0f;
            }
        }
    }
}

// ---------------------------------------------------------------------------
extern "C" void kernel_launch(void* const* d_in, const int* in_sizes, int n_in,
                              void* d_out, int out_size) {
    const float* boxes = (const float*)d_in[0];
    const float* cls   = (const float*)d_in[1];
    const float* rot   = (const float*)d_in[2];
    const float* tr    = (const float*)d_in[3];
    float* out = (float*)d_out;

    k_scan<<<2048, 256>>>(cls);
    k_select<<<PAIRS, 256>>>(cls, boxes);
    k_merge<<<BB, 256>>>(boxes, rot, tr, out);
}